// round 2
// baseline (speedup 1.0000x reference)
#include <cuda_runtime.h>
#include <math.h>

// Problem constants (fixed shapes for this bench)
#define Hh 128
#define Ww 128
#define Nn (Hh*Ww)      // 16384 tokens
#define Cc 64           // channels
#define NHEAD 4
#define HDIM 16
#define TT 64           // tokens per tile
#define TILES (Nn/TT)   // 256 tiles per batch
#define PB 64           // blocks per batch in k-pass (each handles TILES/PB tiles)
#define BMAX 16

// Deterministic scratch (no allocations allowed)
__device__ float g_part_kv[BMAX*PB*1024];   // per-block kv partials
__device__ float g_part_ks[BMAX*PB*64];     // per-block ksum partials
__device__ float g_kvn[BMAX*1024];          // kv / n
__device__ float g_kmean[BMAX*64];          // ksum / n

__device__ __forceinline__ float elu1(float v) { return v > 0.f ? v + 1.f : expf(v); }

__device__ __forceinline__ float dot4(float acc, float4 a, float4 w4) {
    return fmaf(a.x, w4.x, fmaf(a.y, w4.y, fmaf(a.z, w4.z, fmaf(a.w, w4.w, acc))));
}

// ln(10000)/16
#define LN1E4_OVER16 0.57564627324851145f

// ---------------------------------------------------------------------------
// Pass 1: per-token k = elu(x @ Wk^T + bk)+1 ; ksum += k ; rope(k) ;
//         kv += outer(k_rope, v) accumulated in registers, partials to gmem.
// grid (PB, B), block 256. smem: Wk[64][68], xs[64][68], ks[64][68]
// ---------------------------------------------------------------------------
__global__ __launch_bounds__(256) void k_pass(const float* __restrict__ x,
                                              const float* __restrict__ qkw,
                                              const float* __restrict__ qkb) {
    extern __shared__ float sm[];
    float (*sW)[68] = (float (*)[68])sm;
    float (*xs)[68] = (float (*)[68])(sm + 64 * 68);
    float (*ks)[68] = (float (*)[68])(sm + 2 * 64 * 68);

    const int b  = blockIdx.y;
    const int pb = blockIdx.x;
    const int tid = threadIdx.x;

    // Load Wk (rows 64..127 of qk_w)
    for (int i = tid; i < 64 * 64; i += 256) {
        int f = i >> 6, ch = i & 63;
        sW[f][ch] = qkw[(64 + f) * 64 + ch];
    }

    const int ff = tid & 15;          // feature group (4 features)
    const int tt = tid >> 4;          // token group (4 tokens)
    const int f0 = ff * 4;
    const int tb = tt * 4;

    // RoPE constants for this thread's two channel-pairs
    const int mp0 = ff * 2, mp1 = ff * 2 + 1;
    const float th0 = expf(-(float)(mp0 & 15) * LN1E4_OVER16);
    const float th1 = expf(-(float)(mp1 & 15) * LN1E4_OVER16);
    const bool useH0 = (mp0 < 16), useH1 = (mp1 < 16);

    const float bias0 = qkb[64 + f0 + 0];
    const float bias1 = qkb[64 + f0 + 1];
    const float bias2 = qkb[64 + f0 + 2];
    const float bias3 = qkb[64 + f0 + 3];

    float ksum[4] = {0.f, 0.f, 0.f, 0.f};

    // kv ownership: 2x2 block of (d,e) for one head
    const int e0 = (tid & 7) * 2;
    const int d0 = ((tid >> 3) & 7) * 2;
    const int hd = tid >> 6;
    float kv00 = 0.f, kv01 = 0.f, kv10 = 0.f, kv11 = 0.f;

    const float* xb = x + (size_t)b * Nn * Cc;

    for (int tile = pb; tile < TILES; tile += PB) {
        const int token0 = tile * TT;
        __syncthreads();  // protect xs/ks from previous iteration readers (and sW on iter 0)

        // load x tile (vectorized, coalesced)
        for (int i = tid; i < TT * 16; i += 256) {
            int t = i >> 4, c4 = i & 15;
            float4 v = *(const float4*)(xb + (size_t)(token0 + t) * Cc + c4 * 4);
            *(float4*)&xs[t][c4 * 4] = v;
        }
        __syncthreads();

        // GEMM: 4 tokens x 4 features, K=64
        float acc[4][4] = {};
#pragma unroll
        for (int c4 = 0; c4 < 16; c4++) {
            float4 a0 = *(float4*)&xs[tb + 0][c4 * 4];
            float4 a1 = *(float4*)&xs[tb + 1][c4 * 4];
            float4 a2 = *(float4*)&xs[tb + 2][c4 * 4];
            float4 a3 = *(float4*)&xs[tb + 3][c4 * 4];
            float4 w0 = *(float4*)&sW[f0 + 0][c4 * 4];
            float4 w1 = *(float4*)&sW[f0 + 1][c4 * 4];
            float4 w2 = *(float4*)&sW[f0 + 2][c4 * 4];
            float4 w3 = *(float4*)&sW[f0 + 3][c4 * 4];
            acc[0][0] = dot4(acc[0][0], a0, w0); acc[0][1] = dot4(acc[0][1], a0, w1);
            acc[0][2] = dot4(acc[0][2], a0, w2); acc[0][3] = dot4(acc[0][3], a0, w3);
            acc[1][0] = dot4(acc[1][0], a1, w0); acc[1][1] = dot4(acc[1][1], a1, w1);
            acc[1][2] = dot4(acc[1][2], a1, w2); acc[1][3] = dot4(acc[1][3], a1, w3);
            acc[2][0] = dot4(acc[2][0], a2, w0); acc[2][1] = dot4(acc[2][1], a2, w1);
            acc[2][2] = dot4(acc[2][2], a2, w2); acc[2][3] = dot4(acc[2][3], a2, w3);
            acc[3][0] = dot4(acc[3][0], a3, w0); acc[3][1] = dot4(acc[3][1], a3, w1);
            acc[3][2] = dot4(acc[3][2], a3, w2); acc[3][3] = dot4(acc[3][3], a3, w3);
        }

        // epilogue: elu+1, ksum, rope, store k_rope
#pragma unroll
        for (int i = 0; i < 4; i++) {
            int token = token0 + tb + i;
            float hh = (float)(token >> 7);
            float ww = (float)(token & 127);
            float k0 = elu1(acc[i][0] + bias0);
            float k1 = elu1(acc[i][1] + bias1);
            float k2 = elu1(acc[i][2] + bias2);
            float k3 = elu1(acc[i][3] + bias3);
            ksum[0] += k0; ksum[1] += k1; ksum[2] += k2; ksum[3] += k3;
            float s0, c0, s1, c1;
            sincosf((useH0 ? hh : ww) * th0, &s0, &c0);
            sincosf((useH1 ? hh : ww) * th1, &s1, &c1);
            ks[tb + i][f0 + 0] = k0 * c0 - k1 * s0;
            ks[tb + i][f0 + 1] = k0 * s0 + k1 * c0;
            ks[tb + i][f0 + 2] = k2 * c1 - k3 * s1;
            ks[tb + i][f0 + 3] = k2 * s1 + k3 * c1;
        }
        __syncthreads();

        // kv accumulate: kv[d][e] += k_rope[t][d] * v[t][e]
#pragma unroll 8
        for (int t = 0; t < TT; t++) {
            float2 kk = *(float2*)&ks[t][hd * 16 + d0];
            float2 vv = *(float2*)&xs[t][hd * 16 + e0];
            kv00 = fmaf(kk.x, vv.x, kv00);
            kv01 = fmaf(kk.x, vv.y, kv01);
            kv10 = fmaf(kk.y, vv.x, kv10);
            kv11 = fmaf(kk.y, vv.y, kv11);
        }
    }

    // write kv partials (each block owns its slot -> deterministic)
    float* pkv = g_part_kv + ((size_t)(b * PB + pb)) * 1024;
    int base = hd * 256 + d0 * 16 + e0;
    pkv[base + 0]  = kv00;
    pkv[base + 1]  = kv01;
    pkv[base + 16] = kv10;
    pkv[base + 17] = kv11;

    // ksum block reduction (deterministic fixed order), reuse ks smem
    __syncthreads();
    float* red = &ks[0][0];
#pragma unroll
    for (int j = 0; j < 4; j++) red[(f0 + j) * 16 + tt] = ksum[j];
    __syncthreads();
    if (tid < 64) {
        float s = 0.f;
#pragma unroll
        for (int g = 0; g < 16; g++) s += red[tid * 16 + g];
        g_part_ks[(size_t)(b * PB + pb) * 64 + tid] = s;
    }
}

// ---------------------------------------------------------------------------
// Pass 2: reduce partials -> kv/n and k_mean. grid B, block 256.
// ---------------------------------------------------------------------------
__global__ __launch_bounds__(256) void reduce_pass() {
    const int b = blockIdx.x;
    const int tid = threadIdx.x;
    const float invN = 1.0f / (float)Nn;
    for (int e = tid; e < 1024; e += 256) {
        float s = 0.f;
        for (int p = 0; p < PB; p++) s += g_part_kv[(size_t)(b * PB + p) * 1024 + e];
        g_kvn[b * 1024 + e] = s * invN;
    }
    if (tid < 64) {
        float s = 0.f;
        for (int p = 0; p < PB; p++) s += g_part_ks[(size_t)(b * PB + p) * 64 + tid];
        g_kmean[b * 64 + tid] = s * invN;
    }
}

// ---------------------------------------------------------------------------
// Pass 3: q = elu(x @ Wq^T + bq)+1 ; z = 1/(q . k_mean + 1e-6) ; rope(q);
// out = z * q_rope @ kvn + lepe(3x3 depthwise) ; write NCHW.
// grid (TILES, B), block 256.
// ---------------------------------------------------------------------------
__global__ __launch_bounds__(256) void q_pass(const float* __restrict__ x,
                                              const float* __restrict__ qkw,
                                              const float* __restrict__ qkb,
                                              const float* __restrict__ lw,
                                              const float* __restrict__ lb,
                                              float* __restrict__ out) {
    extern __shared__ float sm[];
    float (*sW)[68]  = (float (*)[68])sm;                   // Wq, then lepe buffer
    float (*xs)[68]  = (float (*)[68])(sm + 64 * 68);       // x tile, then attn out
    float (*qs)[68]  = (float (*)[68])(sm + 2 * 64 * 68);   // q_rope
    float* skv       = sm + 3 * 64 * 68;                    // 1024
    float* skm       = skv + 1024;                          // 64
    float (*szp)[17] = (float (*)[17])(skm + 64);           // 64*17
    float (*zz)[4]   = (float (*)[4])(skm + 64 + 64 * 17);  // 64*4

    const int b = blockIdx.y;
    const int tile = blockIdx.x;
    const int tid = threadIdx.x;
    const int token0 = tile * TT;
    const float* xb = x + (size_t)b * Nn * Cc;

    // loads
    for (int i = tid; i < 64 * 64; i += 256) {
        int f = i >> 6, ch = i & 63;
        sW[f][ch] = qkw[f * 64 + ch];
    }
    for (int i = tid; i < 1024; i += 256) skv[i] = g_kvn[b * 1024 + i];
    if (tid < 64) skm[tid] = g_kmean[b * 64 + tid];
    for (int i = tid; i < TT * 16; i += 256) {
        int t = i >> 4, c4 = i & 15;
        float4 v = *(const float4*)(xb + (size_t)(token0 + t) * Cc + c4 * 4);
        *(float4*)&xs[t][c4 * 4] = v;
    }
    __syncthreads();

    const int ff = tid & 15;
    const int tt = tid >> 4;
    const int f0 = ff * 4;
    const int tb = tt * 4;

    const int mp0 = ff * 2, mp1 = ff * 2 + 1;
    const float th0 = expf(-(float)(mp0 & 15) * LN1E4_OVER16);
    const float th1 = expf(-(float)(mp1 & 15) * LN1E4_OVER16);
    const bool useH0 = (mp0 < 16), useH1 = (mp1 < 16);

    const float bias0 = qkb[f0 + 0];
    const float bias1 = qkb[f0 + 1];
    const float bias2 = qkb[f0 + 2];
    const float bias3 = qkb[f0 + 3];

    // GEMM q
    float acc[4][4] = {};
#pragma unroll
    for (int c4 = 0; c4 < 16; c4++) {
        float4 a0 = *(float4*)&xs[tb + 0][c4 * 4];
        float4 a1 = *(float4*)&xs[tb + 1][c4 * 4];
        float4 a2 = *(float4*)&xs[tb + 2][c4 * 4];
        float4 a3 = *(float4*)&xs[tb + 3][c4 * 4];
        float4 w0 = *(float4*)&sW[f0 + 0][c4 * 4];
        float4 w1 = *(float4*)&sW[f0 + 1][c4 * 4];
        float4 w2 = *(float4*)&sW[f0 + 2][c4 * 4];
        float4 w3 = *(float4*)&sW[f0 + 3][c4 * 4];
        acc[0][0] = dot4(acc[0][0], a0, w0); acc[0][1] = dot4(acc[0][1], a0, w1);
        acc[0][2] = dot4(acc[0][2], a0, w2); acc[0][3] = dot4(acc[0][3], a0, w3);
        acc[1][0] = dot4(acc[1][0], a1, w0); acc[1][1] = dot4(acc[1][1], a1, w1);
        acc[1][2] = dot4(acc[1][2], a1, w2); acc[1][3] = dot4(acc[1][3], a1, w3);
        acc[2][0] = dot4(acc[2][0], a2, w0); acc[2][1] = dot4(acc[2][1], a2, w1);
        acc[2][2] = dot4(acc[2][2], a2, w2); acc[2][3] = dot4(acc[2][3], a2, w3);
        acc[3][0] = dot4(acc[3][0], a3, w0); acc[3][1] = dot4(acc[3][1], a3, w1);
        acc[3][2] = dot4(acc[3][2], a3, w2); acc[3][3] = dot4(acc[3][3], a3, w3);
    }

    const float km0 = skm[f0 + 0], km1 = skm[f0 + 1], km2 = skm[f0 + 2], km3 = skm[f0 + 3];

    // epilogue: elu+1, z partials, rope, store q_rope
#pragma unroll
    for (int i = 0; i < 4; i++) {
        int token = token0 + tb + i;
        float hh = (float)(token >> 7);
        float ww = (float)(token & 127);
        float q0 = elu1(acc[i][0] + bias0);
        float q1 = elu1(acc[i][1] + bias1);
        float q2 = elu1(acc[i][2] + bias2);
        float q3 = elu1(acc[i][3] + bias3);
        szp[tb + i][ff] = q0 * km0 + q1 * km1 + q2 * km2 + q3 * km3;
        float s0, c0, s1, c1;
        sincosf((useH0 ? hh : ww) * th0, &s0, &c0);
        sincosf((useH1 ? hh : ww) * th1, &s1, &c1);
        qs[tb + i][f0 + 0] = q0 * c0 - q1 * s0;
        qs[tb + i][f0 + 1] = q0 * s0 + q1 * c0;
        qs[tb + i][f0 + 2] = q2 * c1 - q3 * s1;
        qs[tb + i][f0 + 3] = q2 * s1 + q3 * c1;
    }
    __syncthreads();

    // z reduction (deterministic)
    {
        int t = tid & 63, hd4 = tid >> 6;
        float s = szp[t][hd4 * 4] + szp[t][hd4 * 4 + 1] + szp[t][hd4 * 4 + 2] + szp[t][hd4 * 4 + 3];
        zz[t][hd4] = 1.0f / (s + 1e-6f);
    }
    __syncthreads();

    // attention readout: thread (t, hd); write into xs (x tile is dead)
    {
        int t = tid & 63, hd = tid >> 6;
        float qd[16];
#pragma unroll
        for (int d = 0; d < 16; d++) qd[d] = qs[t][hd * 16 + d];
        float zv = zz[t][hd];
        const float* kvh = skv + hd * 256;
        float accv[16];
#pragma unroll
        for (int e = 0; e < 16; e++) accv[e] = 0.f;
#pragma unroll
        for (int d = 0; d < 16; d++) {
#pragma unroll
            for (int e = 0; e < 16; e++) accv[e] = fmaf(qd[d], kvh[d * 16 + e], accv[e]);
        }
        __syncthreads();  // ensure all reads of xs (GEMM inputs gone) done; xs reuse
#pragma unroll
        for (int e = 0; e < 16; e++) xs[t][hd * 16 + e] = accv[e] * zv;
    }

    // lepe: channel-major mapping (coalesced x reads); write into sW region
    {
        int ch = tid & 63, tg = tid >> 6;
        float w9[9];
#pragma unroll
        for (int k = 0; k < 9; k++) w9[k] = lw[ch * 9 + k];
        float bias = lb[ch];
        int hh = token0 >> 7;
        int ww0 = token0 & 127;
        for (int t = tg; t < TT; t += 4) {
            int wwc = ww0 + t;
            float s = bias;
#pragma unroll
            for (int dy = -1; dy <= 1; dy++) {
                int gh = hh + dy;
                if ((unsigned)gh < (unsigned)Hh) {
#pragma unroll
                    for (int dx = -1; dx <= 1; dx++) {
                        int gw = wwc + dx;
                        if ((unsigned)gw < (unsigned)Ww)
                            s = fmaf(w9[(dy + 1) * 3 + (dx + 1)],
                                     __ldg(xb + (size_t)(gh * Ww + gw) * Cc + ch), s);
                    }
                }
            }
            sW[t][ch] = s;
        }
    }
    __syncthreads();

    // write NCHW, coalesced over tokens
    {
        int t = tid & 63, hd = tid >> 6;
        int token = token0 + t;
        float* ob = out + (size_t)b * Cc * Nn;
#pragma unroll
        for (int j = 0; j < 16; j++) {
            int ch = hd * 16 + j;
            ob[(size_t)ch * Nn + token] = xs[t][ch] + sW[t][ch];
        }
    }
}

// ---------------------------------------------------------------------------
extern "C" void kernel_launch(void* const* d_in, const int* in_sizes, int n_in,
                              void* d_out, int out_size) {
    const float* x   = (const float*)d_in[0];
    // d_in[1]=h, d_in[2]=w (scalars on device; shapes fixed for this bench)
    const float* qkw = (const float*)d_in[3];
    const float* qkb = (const float*)d_in[4];
    const float* lw  = (const float*)d_in[5];
    const float* lb  = (const float*)d_in[6];
    float* out = (float*)d_out;

    int B = in_sizes[0] / (Nn * Cc);
    if (B > BMAX) B = BMAX;

    const int SMEM_K = 3 * 64 * 68 * sizeof(float);                       // 52224
    const int SMEM_Q = (3 * 64 * 68 + 1024 + 64 + 64 * 17 + 64 * 4) * sizeof(float); // 61952

    cudaFuncSetAttribute(k_pass, cudaFuncAttributeMaxDynamicSharedMemorySize, SMEM_K);
    cudaFuncSetAttribute(q_pass, cudaFuncAttributeMaxDynamicSharedMemorySize, SMEM_Q);

    k_pass<<<dim3(PB, B), 256, SMEM_K>>>(x, qkw, qkb);
    reduce_pass<<<B, 256>>>();
    q_pass<<<dim3(TILES, B), 256, SMEM_Q>>>(x, qkw, qkb, lw, lb, out);
}

// round 3
// speedup vs baseline: 1.7691x; 1.7691x over previous
#include <cuda_runtime.h>
#include <math.h>

#define Hh 128
#define Ww 128
#define Nn (Hh*Ww)      // 16384
#define Cc 64
#define TT 64           // tokens per tile
#define TILES (Nn/TT)   // 256
#define PB 64           // k_pass blocks per batch
#define BMAX 16

// Deterministic scratch
__device__ float g_part_kv[BMAX*PB*1024];
__device__ float g_part_ks[BMAX*PB*64];
__device__ float g_kvn[BMAX*1024];
__device__ float g_kmean[BMAX*64];
__device__ float g_cos[2048];   // [pos 0..127][k 0..15]
__device__ float g_sin[2048];

#define LN1E4_OVER16 0.57564627324851145f

__device__ __forceinline__ float elu1(float v) { return v > 0.f ? v + 1.f : __expf(v); }

__device__ __forceinline__ unsigned long long pack2(float lo, float hi) {
    unsigned long long r;
    asm("mov.b64 %0, {%1,%2};" : "=l"(r) : "f"(lo), "f"(hi));
    return r;
}
__device__ __forceinline__ float2 unpack2(unsigned long long v) {
    float2 r;
    asm("mov.b64 {%0,%1}, %2;" : "=f"(r.x), "=f"(r.y) : "l"(v));
    return r;
}
__device__ __forceinline__ void fma2(unsigned long long& d, unsigned long long a, unsigned long long b) {
    asm("fma.rn.f32x2 %0, %1, %2, %0;" : "+l"(d) : "l"(a), "l"(b));
}

// ---------------------------------------------------------------------------
__global__ void init_tables() {
    int idx = threadIdx.x + blockIdx.x * 256;
    if (idx < 2048) {
        int pos = idx >> 4, k = idx & 15;
        float theta = expf(-(float)k * LN1E4_OVER16);
        float ang = (float)pos * theta;
        g_cos[idx] = cosf(ang);
        g_sin[idx] = sinf(ang);
    }
}

// ---------------------------------------------------------------------------
// k_pass smem (floats): Wi 4096 | xs 64x68 | ks 64x68 | cos 2048 | sin 2048
// ---------------------------------------------------------------------------
__global__ __launch_bounds__(256) void k_pass(const float* __restrict__ x,
                                              const float* __restrict__ qkw,
                                              const float* __restrict__ qkb) {
    extern __shared__ float sm[];
    float4* sWi4 = (float4*)sm;
    const ulonglong2* sW2 = (const ulonglong2*)sm;
    float (*xs)[68] = (float (*)[68])(sm + 4096);
    float (*ks)[68] = (float (*)[68])(sm + 8448);
    float* scos = sm + 12800;
    float* ssin = sm + 14848;

    const int b  = blockIdx.y;
    const int pb = blockIdx.x;
    const int tid = threadIdx.x;

    // W interleaved-granule layout: entry [c4*64 + (f&3)*16 + (f>>2)] = W[f][c4*4..+3]
    for (int i = tid; i < 1024; i += 256) {
        int f = i >> 4, c4 = i & 15;
        float4 v = *(const float4*)(qkw + (size_t)(64 + f) * 64 + c4 * 4);
        sWi4[c4 * 64 + (f & 3) * 16 + (f >> 2)] = v;
    }
    for (int i = tid; i < 2048; i += 256) { scos[i] = g_cos[i]; ssin[i] = g_sin[i]; }

    const int ff = tid & 15;
    const int tt = tid >> 4;
    const int f0 = ff * 4;
    const int tb = tt * 4;

    const int kid0 = (2 * ff) & 15, kid1 = (2 * ff + 1) & 15;
    const bool useH = (ff < 8);

    const float bias0 = qkb[64 + f0 + 0];
    const float bias1 = qkb[64 + f0 + 1];
    const float bias2 = qkb[64 + f0 + 2];
    const float bias3 = qkb[64 + f0 + 3];

    float ksum[4] = {0.f, 0.f, 0.f, 0.f};

    const int e0 = (tid & 7) * 2;
    const int d0 = ((tid >> 3) & 7) * 2;
    const int hd = tid >> 6;
    float kv00 = 0.f, kv01 = 0.f, kv10 = 0.f, kv11 = 0.f;

    const float* xb = x + (size_t)b * Nn * Cc;

    for (int tile = pb; tile < TILES; tile += PB) {
        const int token0 = tile * TT;
        __syncthreads();

        for (int i = tid; i < TT * 16; i += 256) {
            int t = i >> 4, c4 = i & 15;
            float4 v = *(const float4*)(xb + (size_t)(token0 + t) * Cc + c4 * 4);
            *(float4*)&xs[t][c4 * 4] = v;
        }
        __syncthreads();

        // GEMM 4 tokens x 4 features, packed f32x2
        unsigned long long acc2[4][4] = {};
#pragma unroll
        for (int c4 = 0; c4 < 16; c4++) {
            ulonglong2 a0 = *(const ulonglong2*)&xs[tb + 0][c4 * 4];
            ulonglong2 a1 = *(const ulonglong2*)&xs[tb + 1][c4 * 4];
            ulonglong2 a2 = *(const ulonglong2*)&xs[tb + 2][c4 * 4];
            ulonglong2 a3 = *(const ulonglong2*)&xs[tb + 3][c4 * 4];
            ulonglong2 w0 = sW2[c4 * 64 + 0 * 16 + ff];
            ulonglong2 w1 = sW2[c4 * 64 + 1 * 16 + ff];
            ulonglong2 w2 = sW2[c4 * 64 + 2 * 16 + ff];
            ulonglong2 w3 = sW2[c4 * 64 + 3 * 16 + ff];
            fma2(acc2[0][0], a0.x, w0.x); fma2(acc2[0][0], a0.y, w0.y);
            fma2(acc2[0][1], a0.x, w1.x); fma2(acc2[0][1], a0.y, w1.y);
            fma2(acc2[0][2], a0.x, w2.x); fma2(acc2[0][2], a0.y, w2.y);
            fma2(acc2[0][3], a0.x, w3.x); fma2(acc2[0][3], a0.y, w3.y);
            fma2(acc2[1][0], a1.x, w0.x); fma2(acc2[1][0], a1.y, w0.y);
            fma2(acc2[1][1], a1.x, w1.x); fma2(acc2[1][1], a1.y, w1.y);
            fma2(acc2[1][2], a1.x, w2.x); fma2(acc2[1][2], a1.y, w2.y);
            fma2(acc2[1][3], a1.x, w3.x); fma2(acc2[1][3], a1.y, w3.y);
            fma2(acc2[2][0], a2.x, w0.x); fma2(acc2[2][0], a2.y, w0.y);
            fma2(acc2[2][1], a2.x, w1.x); fma2(acc2[2][1], a2.y, w1.y);
            fma2(acc2[2][2], a2.x, w2.x); fma2(acc2[2][2], a2.y, w2.y);
            fma2(acc2[2][3], a2.x, w3.x); fma2(acc2[2][3], a2.y, w3.y);
            fma2(acc2[3][0], a3.x, w0.x); fma2(acc2[3][0], a3.y, w0.y);
            fma2(acc2[3][1], a3.x, w1.x); fma2(acc2[3][1], a3.y, w1.y);
            fma2(acc2[3][2], a3.x, w2.x); fma2(acc2[3][2], a3.y, w2.y);
            fma2(acc2[3][3], a3.x, w3.x); fma2(acc2[3][3], a3.y, w3.y);
        }
        float acc[4][4];
#pragma unroll
        for (int i = 0; i < 4; i++)
#pragma unroll
            for (int j = 0; j < 4; j++) {
                float2 p = unpack2(acc2[i][j]);
                acc[i][j] = p.x + p.y;
            }

        // epilogue: elu+1, ksum, rope (table), store k_rope
#pragma unroll
        for (int i = 0; i < 4; i++) {
            int token = token0 + tb + i;
            int pos = useH ? (token >> 7) : (token & 127);
            float k0 = elu1(acc[i][0] + bias0);
            float k1 = elu1(acc[i][1] + bias1);
            float k2 = elu1(acc[i][2] + bias2);
            float k3 = elu1(acc[i][3] + bias3);
            ksum[0] += k0; ksum[1] += k1; ksum[2] += k2; ksum[3] += k3;
            float c0 = scos[pos * 16 + kid0], s0 = ssin[pos * 16 + kid0];
            float c1 = scos[pos * 16 + kid1], s1 = ssin[pos * 16 + kid1];
            ks[tb + i][f0 + 0] = k0 * c0 - k1 * s0;
            ks[tb + i][f0 + 1] = k0 * s0 + k1 * c0;
            ks[tb + i][f0 + 2] = k2 * c1 - k3 * s1;
            ks[tb + i][f0 + 3] = k2 * s1 + k3 * c1;
        }
        __syncthreads();

        // kv accumulate: kv[d][e] += k_rope[t][d] * v[t][e]
#pragma unroll 8
        for (int t = 0; t < TT; t++) {
            float2 kk = *(float2*)&ks[t][hd * 16 + d0];
            float2 vv = *(float2*)&xs[t][hd * 16 + e0];
            kv00 = fmaf(kk.x, vv.x, kv00);
            kv01 = fmaf(kk.x, vv.y, kv01);
            kv10 = fmaf(kk.y, vv.x, kv10);
            kv11 = fmaf(kk.y, vv.y, kv11);
        }
    }

    float* pkv = g_part_kv + ((size_t)(b * PB + pb)) * 1024;
    int base = hd * 256 + d0 * 16 + e0;
    pkv[base + 0]  = kv00;
    pkv[base + 1]  = kv01;
    pkv[base + 16] = kv10;
    pkv[base + 17] = kv11;

    __syncthreads();
    float* red = &ks[0][0];
#pragma unroll
    for (int j = 0; j < 4; j++) red[(f0 + j) * 16 + tt] = ksum[j];
    __syncthreads();
    if (tid < 64) {
        float s = 0.f;
#pragma unroll
        for (int g = 0; g < 16; g++) s += red[tid * 16 + g];
        g_part_ks[(size_t)(b * PB + pb) * 64 + tid] = s;
    }
}

// ---------------------------------------------------------------------------
__global__ __launch_bounds__(256) void reduce_pass() {
    const int b = blockIdx.x;
    const int tid = threadIdx.x;
    const float invN = 1.0f / (float)Nn;
    for (int e = tid; e < 1024; e += 256) {
        float s = 0.f;
        for (int p = 0; p < PB; p++) s += g_part_kv[(size_t)(b * PB + p) * 1024 + e];
        g_kvn[b * 1024 + e] = s * invN;
    }
    if (tid < 64) {
        float s = 0.f;
        for (int p = 0; p < PB; p++) s += g_part_ks[(size_t)(b * PB + p) * 64 + tid];
        g_kmean[b * 64 + tid] = s * invN;
    }
}

// ---------------------------------------------------------------------------
// q_pass smem (floats):
//  [0,4160)      Wi (4096, granule layout) -> later lepe buf (64x65)
//  [4160,8512)   xs 64x68
//  [8512,12864)  qs 64x68  -> later attn buf (64x65)
//  [12864,13888) kv 1024
//  [13888,13952) km 64
//  [13952,15040) szp 64x17
//  [15040,15296) zz 64x4
//  [15296,17344) cos ; [17344,19392) sin
// ---------------------------------------------------------------------------
__global__ __launch_bounds__(256) void q_pass(const float* __restrict__ x,
                                              const float* __restrict__ qkw,
                                              const float* __restrict__ qkb,
                                              const float* __restrict__ lw,
                                              const float* __restrict__ lb,
                                              float* __restrict__ out) {
    extern __shared__ float sm[];
    float4* sWi4 = (float4*)sm;
    const ulonglong2* sW2 = (const ulonglong2*)sm;
    float* slepe = sm;                                    // 64x65 after GEMM
    float (*xs)[68] = (float (*)[68])(sm + 4160);
    float (*qs)[68] = (float (*)[68])(sm + 8512);
    float* abuf = sm + 8512;                              // 64x65 after readout
    float* skv  = sm + 12864;
    float* skm  = sm + 13888;
    float (*szp)[17] = (float (*)[17])(sm + 13952);
    float* zz   = sm + 15040;
    float* scos = sm + 15296;
    float* ssin = sm + 17344;

    const int b = blockIdx.y;
    const int tile = blockIdx.x;
    const int tid = threadIdx.x;
    const int token0 = tile * TT;
    const float* xb = x + (size_t)b * Nn * Cc;

    for (int i = tid; i < 1024; i += 256) {
        int f = i >> 4, c4 = i & 15;
        float4 v = *(const float4*)(qkw + (size_t)f * 64 + c4 * 4);
        sWi4[c4 * 64 + (f & 3) * 16 + (f >> 2)] = v;
    }
    for (int i = tid; i < 2048; i += 256) { scos[i] = g_cos[i]; ssin[i] = g_sin[i]; }
    for (int i = tid; i < 1024; i += 256) skv[i] = g_kvn[b * 1024 + i];
    if (tid < 64) skm[tid] = g_kmean[b * 64 + tid];
    for (int i = tid; i < TT * 16; i += 256) {
        int t = i >> 4, c4 = i & 15;
        float4 v = *(const float4*)(xb + (size_t)(token0 + t) * Cc + c4 * 4);
        *(float4*)&xs[t][c4 * 4] = v;
    }
    __syncthreads();

    const int ff = tid & 15;
    const int tt = tid >> 4;
    const int f0 = ff * 4;
    const int tb = tt * 4;
    const int kid0 = (2 * ff) & 15, kid1 = (2 * ff + 1) & 15;
    const bool useH = (ff < 8);

    const float bias0 = qkb[f0 + 0];
    const float bias1 = qkb[f0 + 1];
    const float bias2 = qkb[f0 + 2];
    const float bias3 = qkb[f0 + 3];

    unsigned long long acc2[4][4] = {};
#pragma unroll
    for (int c4 = 0; c4 < 16; c4++) {
        ulonglong2 a0 = *(const ulonglong2*)&xs[tb + 0][c4 * 4];
        ulonglong2 a1 = *(const ulonglong2*)&xs[tb + 1][c4 * 4];
        ulonglong2 a2 = *(const ulonglong2*)&xs[tb + 2][c4 * 4];
        ulonglong2 a3 = *(const ulonglong2*)&xs[tb + 3][c4 * 4];
        ulonglong2 w0 = sW2[c4 * 64 + 0 * 16 + ff];
        ulonglong2 w1 = sW2[c4 * 64 + 1 * 16 + ff];
        ulonglong2 w2 = sW2[c4 * 64 + 2 * 16 + ff];
        ulonglong2 w3 = sW2[c4 * 64 + 3 * 16 + ff];
        fma2(acc2[0][0], a0.x, w0.x); fma2(acc2[0][0], a0.y, w0.y);
        fma2(acc2[0][1], a0.x, w1.x); fma2(acc2[0][1], a0.y, w1.y);
        fma2(acc2[0][2], a0.x, w2.x); fma2(acc2[0][2], a0.y, w2.y);
        fma2(acc2[0][3], a0.x, w3.x); fma2(acc2[0][3], a0.y, w3.y);
        fma2(acc2[1][0], a1.x, w0.x); fma2(acc2[1][0], a1.y, w0.y);
        fma2(acc2[1][1], a1.x, w1.x); fma2(acc2[1][1], a1.y, w1.y);
        fma2(acc2[1][2], a1.x, w2.x); fma2(acc2[1][2], a1.y, w2.y);
        fma2(acc2[1][3], a1.x, w3.x); fma2(acc2[1][3], a1.y, w3.y);
        fma2(acc2[2][0], a2.x, w0.x); fma2(acc2[2][0], a2.y, w0.y);
        fma2(acc2[2][1], a2.x, w1.x); fma2(acc2[2][1], a2.y, w1.y);
        fma2(acc2[2][2], a2.x, w2.x); fma2(acc2[2][2], a2.y, w2.y);
        fma2(acc2[2][3], a2.x, w3.x); fma2(acc2[2][3], a2.y, w3.y);
        fma2(acc2[3][0], a3.x, w0.x); fma2(acc2[3][0], a3.y, w0.y);
        fma2(acc2[3][1], a3.x, w1.x); fma2(acc2[3][1], a3.y, w1.y);
        fma2(acc2[3][2], a3.x, w2.x); fma2(acc2[3][2], a3.y, w2.y);
        fma2(acc2[3][3], a3.x, w3.x); fma2(acc2[3][3], a3.y, w3.y);
    }
    float acc[4][4];
#pragma unroll
    for (int i = 0; i < 4; i++)
#pragma unroll
        for (int j = 0; j < 4; j++) {
            float2 p = unpack2(acc2[i][j]);
            acc[i][j] = p.x + p.y;
        }

    const float km0 = skm[f0 + 0], km1 = skm[f0 + 1], km2 = skm[f0 + 2], km3 = skm[f0 + 3];

#pragma unroll
    for (int i = 0; i < 4; i++) {
        int token = token0 + tb + i;
        int pos = useH ? (token >> 7) : (token & 127);
        float q0 = elu1(acc[i][0] + bias0);
        float q1 = elu1(acc[i][1] + bias1);
        float q2 = elu1(acc[i][2] + bias2);
        float q3 = elu1(acc[i][3] + bias3);
        szp[tb + i][ff] = q0 * km0 + q1 * km1 + q2 * km2 + q3 * km3;
        float c0 = scos[pos * 16 + kid0], s0 = ssin[pos * 16 + kid0];
        float c1 = scos[pos * 16 + kid1], s1 = ssin[pos * 16 + kid1];
        qs[tb + i][f0 + 0] = q0 * c0 - q1 * s0;
        qs[tb + i][f0 + 1] = q0 * s0 + q1 * c0;
        qs[tb + i][f0 + 2] = q2 * c1 - q3 * s1;
        qs[tb + i][f0 + 3] = q2 * s1 + q3 * c1;
    }
    __syncthreads();

    // z reduction
    {
        int t = tid & 63, h4 = tid >> 6;
        float s = szp[t][h4 * 4 + 0] + szp[t][h4 * 4 + 1] + szp[t][h4 * 4 + 2] + szp[t][h4 * 4 + 3];
        zz[t * 4 + h4] = 1.0f / (s + 1e-6f);
    }
    __syncthreads();

    // readout: thread = (e 16, tg 2, hd 4, th 2); each computes 16 tokens x 1 e
    float areg[16];
    int rtbase;
    {
        int e  = tid & 15;
        int tg = (tid >> 4) & 1;
        int hd = (tid >> 5) & 3;
        int th = tid >> 7;
        rtbase = (th * 2 + tg) * 16;
        float kvc[16];
#pragma unroll
        for (int d = 0; d < 16; d++) kvc[d] = skv[hd * 256 + d * 16 + e];
        unsigned long long kv2[8];
#pragma unroll
        for (int p = 0; p < 8; p++) kv2[p] = pack2(kvc[2 * p], kvc[2 * p + 1]);
#pragma unroll
        for (int i = 0; i < 16; i++) {
            int t = rtbase + i;
            ulonglong2 q0 = *(const ulonglong2*)&qs[t][hd * 16 + 0];
            ulonglong2 q1 = *(const ulonglong2*)&qs[t][hd * 16 + 4];
            ulonglong2 q2 = *(const ulonglong2*)&qs[t][hd * 16 + 8];
            ulonglong2 q3 = *(const ulonglong2*)&qs[t][hd * 16 + 12];
            unsigned long long a2 = 0ull;
            fma2(a2, q0.x, kv2[0]); fma2(a2, q0.y, kv2[1]);
            fma2(a2, q1.x, kv2[2]); fma2(a2, q1.y, kv2[3]);
            fma2(a2, q2.x, kv2[4]); fma2(a2, q2.y, kv2[5]);
            fma2(a2, q3.x, kv2[6]); fma2(a2, q3.y, kv2[7]);
            float2 p = unpack2(a2);
            areg[i] = (p.x + p.y) * zz[t * 4 + hd];
        }
    }
    __syncthreads();   // all qs reads done; safe to overwrite qs region (abuf) and Wi (slepe)
    {
        int e  = tid & 15;
        int hd = (tid >> 5) & 3;
#pragma unroll
        for (int i = 0; i < 16; i++) abuf[(rtbase + i) * 65 + hd * 16 + e] = areg[i];
    }

    // lepe: thread = (ch 64, tg 4), 16 consecutive w each, sliding window
    {
        int ch = tid & 63;
        int tg = tid >> 6;
        float w9[9];
#pragma unroll
        for (int k = 0; k < 9; k++) w9[k] = lw[ch * 9 + k];
        float bias = lb[ch];
        const int hh = token0 >> 7;
        const int ww0 = token0 & 127;
        const int wstart = ww0 + tg * 16;
        const bool hm = hh > 0, hp = hh < (Hh - 1);
        const float* rm = xb + ((size_t)(hh - 1) * Ww) * Cc + ch;
        const float* r0 = xb + ((size_t)hh * Ww) * Cc + ch;
        const float* rp = xb + ((size_t)(hh + 1) * Ww) * Cc + ch;

        float La, Lb2, Lc, Ma, Mb2, Mc, Ra, Rb2, Rc;
        {
            int gw = wstart - 1;
            if ((unsigned)gw < (unsigned)Ww) {
                La = hm ? rm[(size_t)gw * Cc] : 0.f;
                Lb2 = r0[(size_t)gw * Cc];
                Lc = hp ? rp[(size_t)gw * Cc] : 0.f;
            } else { La = Lb2 = Lc = 0.f; }
            gw = wstart;
            Ma = hm ? rm[(size_t)gw * Cc] : 0.f;
            Mb2 = r0[(size_t)gw * Cc];
            Mc = hp ? rp[(size_t)gw * Cc] : 0.f;
        }
#pragma unroll
        for (int j = 0; j < 16; j++) {
            int gw = wstart + j + 1;
            if ((unsigned)gw < (unsigned)Ww) {
                Ra = hm ? rm[(size_t)gw * Cc] : 0.f;
                Rb2 = r0[(size_t)gw * Cc];
                Rc = hp ? rp[(size_t)gw * Cc] : 0.f;
            } else { Ra = Rb2 = Rc = 0.f; }
            float s = bias;
            s = fmaf(w9[0], La, s);  s = fmaf(w9[1], Ma, s);  s = fmaf(w9[2], Ra, s);
            s = fmaf(w9[3], Lb2, s); s = fmaf(w9[4], Mb2, s); s = fmaf(w9[5], Rb2, s);
            s = fmaf(w9[6], Lc, s);  s = fmaf(w9[7], Mc, s);  s = fmaf(w9[8], Rc, s);
            slepe[(tg * 16 + j) * 65 + ch] = s;
            La = Ma; Lb2 = Mb2; Lc = Mc;
            Ma = Ra; Mb2 = Rb2; Mc = Rc;
        }
    }
    __syncthreads();

    // final NCHW write
    {
        int t = tid & 63, hg = tid >> 6;
        int token = token0 + t;
        float* ob = out + (size_t)b * Cc * Nn;
#pragma unroll
        for (int j = 0; j < 16; j++) {
            int ch = hg * 16 + j;
            ob[(size_t)ch * Nn + token] = abuf[t * 65 + ch] + slepe[t * 65 + ch];
        }
    }
}

// ---------------------------------------------------------------------------
extern "C" void kernel_launch(void* const* d_in, const int* in_sizes, int n_in,
                              void* d_out, int out_size) {
    const float* x   = (const float*)d_in[0];
    const float* qkw = (const float*)d_in[3];
    const float* qkb = (const float*)d_in[4];
    const float* lw  = (const float*)d_in[5];
    const float* lb  = (const float*)d_in[6];
    float* out = (float*)d_out;

    int B = in_sizes[0] / (Nn * Cc);
    if (B > BMAX) B = BMAX;

    const int SMEM_K = 16896 * sizeof(float);   // 67584
    const int SMEM_Q = 19392 * sizeof(float);   // 77568

    cudaFuncSetAttribute(k_pass, cudaFuncAttributeMaxDynamicSharedMemorySize, SMEM_K);
    cudaFuncSetAttribute(q_pass, cudaFuncAttributeMaxDynamicSharedMemorySize, SMEM_Q);

    init_tables<<<8, 256>>>();
    k_pass<<<dim3(PB, B), 256, SMEM_K>>>(x, qkw, qkb);
    reduce_pass<<<B, 256>>>();
    q_pass<<<dim3(TILES, B), 256, SMEM_Q>>>(x, qkw, qkb, lw, lb, out);
}

// round 4
// speedup vs baseline: 1.7732x; 1.0023x over previous
#include <cuda_runtime.h>
#include <math.h>

#define Hh 128
#define Ww 128
#define Nn (Hh*Ww)      // 16384
#define Cc 64
#define TT 64           // tokens per tile
#define TILES (Nn/TT)   // 256
#define PB 128          // k_pass blocks per batch
#define BMAX 16

// Deterministic scratch
__device__ float g_part_kv[BMAX*PB*1024];
__device__ float g_part_ks[BMAX*PB*64];
__device__ float g_kvn[BMAX*1024];
__device__ float g_kmean[BMAX*64];
__device__ float2 g_cs[2048];   // [pos 0..127][k 0..15] -> (cos, sin)

#define LN1E4_OVER16 0.57564627324851145f

__device__ __forceinline__ float elu1(float v) { return v > 0.f ? v + 1.f : __expf(v); }

__device__ __forceinline__ float2 unpack2(unsigned long long v) {
    float2 r;
    asm("mov.b64 {%0,%1}, %2;" : "=f"(r.x), "=f"(r.y) : "l"(v));
    return r;
}
__device__ __forceinline__ void fma2(unsigned long long& d, unsigned long long a, unsigned long long b) {
    asm("fma.rn.f32x2 %0, %1, %2, %0;" : "+l"(d) : "l"(a), "l"(b));
}

// ---------------------------------------------------------------------------
__global__ void init_tables() {
    int idx = threadIdx.x + blockIdx.x * 256;
    if (idx < 2048) {
        int pos = idx >> 4, k = idx & 15;
        float theta = expf(-(float)k * LN1E4_OVER16);
        float ang = (float)pos * theta;
        g_cs[idx] = make_float2(cosf(ang), sinf(ang));
    }
}

// ---------------------------------------------------------------------------
// k_pass smem (floats): Wi 4096 | xs 64x68 | ks 64x68   (51200 B)
// ---------------------------------------------------------------------------
__global__ __launch_bounds__(256, 4) void k_pass(const float* __restrict__ x,
                                                 const float* __restrict__ qkw,
                                                 const float* __restrict__ qkb) {
    extern __shared__ float sm[];
    float4* sWi4 = (float4*)sm;
    const ulonglong2* sW2 = (const ulonglong2*)sm;
    float (*xs)[68] = (float (*)[68])(sm + 4096);
    float (*ks)[68] = (float (*)[68])(sm + 8448);

    const int b  = blockIdx.y;
    const int pb = blockIdx.x;
    const int tid = threadIdx.x;

    // W interleaved-granule layout: entry [c4*64 + (f&3)*16 + (f>>2)] = W[f][c4*4..+3]
    for (int i = tid; i < 1024; i += 256) {
        int f = i >> 4, c4 = i & 15;
        float4 v = *(const float4*)(qkw + (size_t)(64 + f) * 64 + c4 * 4);
        sWi4[c4 * 64 + (f & 3) * 16 + (f >> 2)] = v;
    }

    const int ff = tid & 15;
    const int tt = tid >> 4;
    const int f0 = ff * 4;
    const int tb = tt * 4;

    const int kid0 = (2 * ff) & 15, kid1 = (2 * ff + 1) & 15;
    const bool useH = (ff < 8);

    const float bias0 = qkb[64 + f0 + 0];
    const float bias1 = qkb[64 + f0 + 1];
    const float bias2 = qkb[64 + f0 + 2];
    const float bias3 = qkb[64 + f0 + 3];

    float ksum[4] = {0.f, 0.f, 0.f, 0.f};

    const int e0 = (tid & 7) * 2;
    const int d0 = ((tid >> 3) & 7) * 2;
    const int hd = tid >> 6;
    float kv00 = 0.f, kv01 = 0.f, kv10 = 0.f, kv11 = 0.f;

    const float* xb = x + (size_t)b * Nn * Cc;

    for (int tile = pb; tile < TILES; tile += PB) {
        const int token0 = tile * TT;
        __syncthreads();

        for (int i = tid; i < TT * 16; i += 256) {
            int t = i >> 4, c4 = i & 15;
            float4 v = *(const float4*)(xb + (size_t)(token0 + t) * Cc + c4 * 4);
            *(float4*)&xs[t][c4 * 4] = v;
        }
        __syncthreads();

        unsigned long long acc2[4][4] = {};
#pragma unroll
        for (int c4 = 0; c4 < 16; c4++) {
            ulonglong2 a0 = *(const ulonglong2*)&xs[tb + 0][c4 * 4];
            ulonglong2 a1 = *(const ulonglong2*)&xs[tb + 1][c4 * 4];
            ulonglong2 a2 = *(const ulonglong2*)&xs[tb + 2][c4 * 4];
            ulonglong2 a3 = *(const ulonglong2*)&xs[tb + 3][c4 * 4];
            ulonglong2 w0 = sW2[c4 * 64 + 0 * 16 + ff];
            ulonglong2 w1 = sW2[c4 * 64 + 1 * 16 + ff];
            ulonglong2 w2 = sW2[c4 * 64 + 2 * 16 + ff];
            ulonglong2 w3 = sW2[c4 * 64 + 3 * 16 + ff];
            fma2(acc2[0][0], a0.x, w0.x); fma2(acc2[0][0], a0.y, w0.y);
            fma2(acc2[0][1], a0.x, w1.x); fma2(acc2[0][1], a0.y, w1.y);
            fma2(acc2[0][2], a0.x, w2.x); fma2(acc2[0][2], a0.y, w2.y);
            fma2(acc2[0][3], a0.x, w3.x); fma2(acc2[0][3], a0.y, w3.y);
            fma2(acc2[1][0], a1.x, w0.x); fma2(acc2[1][0], a1.y, w0.y);
            fma2(acc2[1][1], a1.x, w1.x); fma2(acc2[1][1], a1.y, w1.y);
            fma2(acc2[1][2], a1.x, w2.x); fma2(acc2[1][2], a1.y, w2.y);
            fma2(acc2[1][3], a1.x, w3.x); fma2(acc2[1][3], a1.y, w3.y);
            fma2(acc2[2][0], a2.x, w0.x); fma2(acc2[2][0], a2.y, w0.y);
            fma2(acc2[2][1], a2.x, w1.x); fma2(acc2[2][1], a2.y, w1.y);
            fma2(acc2[2][2], a2.x, w2.x); fma2(acc2[2][2], a2.y, w2.y);
            fma2(acc2[2][3], a2.x, w3.x); fma2(acc2[2][3], a2.y, w3.y);
            fma2(acc2[3][0], a3.x, w0.x); fma2(acc2[3][0], a3.y, w0.y);
            fma2(acc2[3][1], a3.x, w1.x); fma2(acc2[3][1], a3.y, w1.y);
            fma2(acc2[3][2], a3.x, w2.x); fma2(acc2[3][2], a3.y, w2.y);
            fma2(acc2[3][3], a3.x, w3.x); fma2(acc2[3][3], a3.y, w3.y);
        }
        float acc[4][4];
#pragma unroll
        for (int i = 0; i < 4; i++)
#pragma unroll
            for (int j = 0; j < 4; j++) {
                float2 p = unpack2(acc2[i][j]);
                acc[i][j] = p.x + p.y;
            }

#pragma unroll
        for (int i = 0; i < 4; i++) {
            int token = token0 + tb + i;
            int pos = useH ? (token >> 7) : (token & 127);
            float k0 = elu1(acc[i][0] + bias0);
            float k1 = elu1(acc[i][1] + bias1);
            float k2 = elu1(acc[i][2] + bias2);
            float k3 = elu1(acc[i][3] + bias3);
            ksum[0] += k0; ksum[1] += k1; ksum[2] += k2; ksum[3] += k3;
            float2 cs0 = __ldg(&g_cs[pos * 16 + kid0]);
            float2 cs1 = __ldg(&g_cs[pos * 16 + kid1]);
            ks[tb + i][f0 + 0] = k0 * cs0.x - k1 * cs0.y;
            ks[tb + i][f0 + 1] = k0 * cs0.y + k1 * cs0.x;
            ks[tb + i][f0 + 2] = k2 * cs1.x - k3 * cs1.y;
            ks[tb + i][f0 + 3] = k2 * cs1.y + k3 * cs1.x;
        }
        __syncthreads();

#pragma unroll 8
        for (int t = 0; t < TT; t++) {
            float2 kk = *(float2*)&ks[t][hd * 16 + d0];
            float2 vv = *(float2*)&xs[t][hd * 16 + e0];
            kv00 = fmaf(kk.x, vv.x, kv00);
            kv01 = fmaf(kk.x, vv.y, kv01);
            kv10 = fmaf(kk.y, vv.x, kv10);
            kv11 = fmaf(kk.y, vv.y, kv11);
        }
    }

    float* pkv = g_part_kv + ((size_t)(b * PB + pb)) * 1024;
    int base = hd * 256 + d0 * 16 + e0;
    pkv[base + 0]  = kv00;
    pkv[base + 1]  = kv01;
    pkv[base + 16] = kv10;
    pkv[base + 17] = kv11;

    __syncthreads();
    float* red = &ks[0][0];
#pragma unroll
    for (int j = 0; j < 4; j++) red[(f0 + j) * 16 + tt] = ksum[j];
    __syncthreads();
    if (tid < 64) {
        float s = 0.f;
#pragma unroll
        for (int g = 0; g < 16; g++) s += red[tid * 16 + g];
        g_part_ks[(size_t)(b * PB + pb) * 64 + tid] = s;
    }
}

// ---------------------------------------------------------------------------
__global__ __launch_bounds__(256) void reduce_pass() {
    const int b = blockIdx.x;
    const int tid = threadIdx.x;
    const float invN = 1.0f / (float)Nn;
    for (int e = tid; e < 1024; e += 256) {
        float s = 0.f;
        for (int p = 0; p < PB; p++) s += g_part_kv[(size_t)(b * PB + p) * 1024 + e];
        g_kvn[b * 1024 + e] = s * invN;
    }
    if (tid < 64) {
        float s = 0.f;
        for (int p = 0; p < PB; p++) s += g_part_ks[(size_t)(b * PB + p) * 64 + tid];
        g_kmean[b * 64 + tid] = s * invN;
    }
}

// ---------------------------------------------------------------------------
// q_pass smem (floats):
//  [0,4160)      Wi (4096) -> later lepe buf (64x65)
//  [4160,8512)   xs 64x68
//  [8512,12864)  qs 64x68  -> later attn buf (64x65)
//  [12864,13888) kv 1024
//  [13888,13952) km 64
//  [13952,15040) szp 64x17
//  [15040,15296) zz 64x4
//  total 15296 floats = 61184 B
// ---------------------------------------------------------------------------
__global__ __launch_bounds__(256, 3) void q_pass(const float* __restrict__ x,
                                                 const float* __restrict__ qkw,
                                                 const float* __restrict__ qkb,
                                                 const float* __restrict__ lw,
                                                 const float* __restrict__ lb,
                                                 float* __restrict__ out) {
    extern __shared__ float sm[];
    float4* sWi4 = (float4*)sm;
    const ulonglong2* sW2 = (const ulonglong2*)sm;
    float* slepe = sm;                                    // 64x65 after GEMM
    float (*xs)[68] = (float (*)[68])(sm + 4160);
    float (*qs)[68] = (float (*)[68])(sm + 8512);
    float* abuf = sm + 8512;                              // 64x65 after readout
    float* skv  = sm + 12864;
    float* skm  = sm + 13888;
    float (*szp)[17] = (float (*)[17])(sm + 13952);
    float* zz   = sm + 15040;

    const int b = blockIdx.y;
    const int tile = blockIdx.x;
    const int tid = threadIdx.x;
    const int token0 = tile * TT;
    const float* xb = x + (size_t)b * Nn * Cc;

    for (int i = tid; i < 1024; i += 256) {
        int f = i >> 4, c4 = i & 15;
        float4 v = *(const float4*)(qkw + (size_t)f * 64 + c4 * 4);
        sWi4[c4 * 64 + (f & 3) * 16 + (f >> 2)] = v;
    }
    for (int i = tid; i < 1024; i += 256) skv[i] = g_kvn[b * 1024 + i];
    if (tid < 64) skm[tid] = g_kmean[b * 64 + tid];
    for (int i = tid; i < TT * 16; i += 256) {
        int t = i >> 4, c4 = i & 15;
        float4 v = *(const float4*)(xb + (size_t)(token0 + t) * Cc + c4 * 4);
        *(float4*)&xs[t][c4 * 4] = v;
    }
    __syncthreads();

    const int ff = tid & 15;
    const int tt = tid >> 4;
    const int f0 = ff * 4;
    const int tb = tt * 4;
    const int kid0 = (2 * ff) & 15, kid1 = (2 * ff + 1) & 15;
    const bool useH = (ff < 8);

    const float bias0 = qkb[f0 + 0];
    const float bias1 = qkb[f0 + 1];
    const float bias2 = qkb[f0 + 2];
    const float bias3 = qkb[f0 + 3];

    unsigned long long acc2[4][4] = {};
#pragma unroll
    for (int c4 = 0; c4 < 16; c4++) {
        ulonglong2 a0 = *(const ulonglong2*)&xs[tb + 0][c4 * 4];
        ulonglong2 a1 = *(const ulonglong2*)&xs[tb + 1][c4 * 4];
        ulonglong2 a2 = *(const ulonglong2*)&xs[tb + 2][c4 * 4];
        ulonglong2 a3 = *(const ulonglong2*)&xs[tb + 3][c4 * 4];
        ulonglong2 w0 = sW2[c4 * 64 + 0 * 16 + ff];
        ulonglong2 w1 = sW2[c4 * 64 + 1 * 16 + ff];
        ulonglong2 w2 = sW2[c4 * 64 + 2 * 16 + ff];
        ulonglong2 w3 = sW2[c4 * 64 + 3 * 16 + ff];
        fma2(acc2[0][0], a0.x, w0.x); fma2(acc2[0][0], a0.y, w0.y);
        fma2(acc2[0][1], a0.x, w1.x); fma2(acc2[0][1], a0.y, w1.y);
        fma2(acc2[0][2], a0.x, w2.x); fma2(acc2[0][2], a0.y, w2.y);
        fma2(acc2[0][3], a0.x, w3.x); fma2(acc2[0][3], a0.y, w3.y);
        fma2(acc2[1][0], a1.x, w0.x); fma2(acc2[1][0], a1.y, w0.y);
        fma2(acc2[1][1], a1.x, w1.x); fma2(acc2[1][1], a1.y, w1.y);
        fma2(acc2[1][2], a1.x, w2.x); fma2(acc2[1][2], a1.y, w2.y);
        fma2(acc2[1][3], a1.x, w3.x); fma2(acc2[1][3], a1.y, w3.y);
        fma2(acc2[2][0], a2.x, w0.x); fma2(acc2[2][0], a2.y, w0.y);
        fma2(acc2[2][1], a2.x, w1.x); fma2(acc2[2][1], a2.y, w1.y);
        fma2(acc2[2][2], a2.x, w2.x); fma2(acc2[2][2], a2.y, w2.y);
        fma2(acc2[2][3], a2.x, w3.x); fma2(acc2[2][3], a2.y, w3.y);
        fma2(acc2[3][0], a3.x, w0.x); fma2(acc2[3][0], a3.y, w0.y);
        fma2(acc2[3][1], a3.x, w1.x); fma2(acc2[3][1], a3.y, w1.y);
        fma2(acc2[3][2], a3.x, w2.x); fma2(acc2[3][2], a3.y, w2.y);
        fma2(acc2[3][3], a3.x, w3.x); fma2(acc2[3][3], a3.y, w3.y);
    }
    float acc[4][4];
#pragma unroll
    for (int i = 0; i < 4; i++)
#pragma unroll
        for (int j = 0; j < 4; j++) {
            float2 p = unpack2(acc2[i][j]);
            acc[i][j] = p.x + p.y;
        }

    const float km0 = skm[f0 + 0], km1 = skm[f0 + 1], km2 = skm[f0 + 2], km3 = skm[f0 + 3];

#pragma unroll
    for (int i = 0; i < 4; i++) {
        int token = token0 + tb + i;
        int pos = useH ? (token >> 7) : (token & 127);
        float q0 = elu1(acc[i][0] + bias0);
        float q1 = elu1(acc[i][1] + bias1);
        float q2 = elu1(acc[i][2] + bias2);
        float q3 = elu1(acc[i][3] + bias3);
        szp[tb + i][ff] = q0 * km0 + q1 * km1 + q2 * km2 + q3 * km3;
        float2 cs0 = __ldg(&g_cs[pos * 16 + kid0]);
        float2 cs1 = __ldg(&g_cs[pos * 16 + kid1]);
        qs[tb + i][f0 + 0] = q0 * cs0.x - q1 * cs0.y;
        qs[tb + i][f0 + 1] = q0 * cs0.y + q1 * cs0.x;
        qs[tb + i][f0 + 2] = q2 * cs1.x - q3 * cs1.y;
        qs[tb + i][f0 + 3] = q2 * cs1.y + q3 * cs1.x;
    }
    __syncthreads();

    // z reduction
    {
        int t = tid & 63, h4 = tid >> 6;
        float s = szp[t][h4 * 4 + 0] + szp[t][h4 * 4 + 1] + szp[t][h4 * 4 + 2] + szp[t][h4 * 4 + 3];
        zz[t * 4 + h4] = 1.0f / (s + 1e-6f);
    }
    __syncthreads();

    // readout: thread = (e 16, tg 2, hd 4, th 2); 16 tokens x 1 e each
    float areg[16];
    int rtbase;
    {
        int e  = tid & 15;
        int tg = (tid >> 4) & 1;
        int hd = (tid >> 5) & 3;
        int th = tid >> 7;
        rtbase = (th * 2 + tg) * 16;
        float kvc[16];
#pragma unroll
        for (int d = 0; d < 16; d++) kvc[d] = skv[hd * 256 + d * 16 + e];
        unsigned long long kv2[8];
#pragma unroll
        for (int p = 0; p < 8; p++) {
            unsigned long long r;
            asm("mov.b64 %0, {%1,%2};" : "=l"(r) : "f"(kvc[2 * p]), "f"(kvc[2 * p + 1]));
            kv2[p] = r;
        }
#pragma unroll
        for (int i = 0; i < 16; i++) {
            int t = rtbase + i;
            ulonglong2 q0 = *(const ulonglong2*)&qs[t][hd * 16 + 0];
            ulonglong2 q1 = *(const ulonglong2*)&qs[t][hd * 16 + 4];
            ulonglong2 q2 = *(const ulonglong2*)&qs[t][hd * 16 + 8];
            ulonglong2 q3 = *(const ulonglong2*)&qs[t][hd * 16 + 12];
            unsigned long long a2 = 0ull;
            fma2(a2, q0.x, kv2[0]); fma2(a2, q0.y, kv2[1]);
            fma2(a2, q1.x, kv2[2]); fma2(a2, q1.y, kv2[3]);
            fma2(a2, q2.x, kv2[4]); fma2(a2, q2.y, kv2[5]);
            fma2(a2, q3.x, kv2[6]); fma2(a2, q3.y, kv2[7]);
            float2 p = unpack2(a2);
            areg[i] = (p.x + p.y) * zz[t * 4 + hd];
        }
    }
    __syncthreads();   // qs reads done; safe to overwrite qs (abuf) and Wi (slepe)
    {
        int e  = tid & 15;
        int hd = (tid >> 5) & 3;
#pragma unroll
        for (int i = 0; i < 16; i++) abuf[(rtbase + i) * 65 + hd * 16 + e] = areg[i];
    }

    // lepe: thread = (ch 64, tg 4), 16 consecutive w each, sliding window
    {
        int ch = tid & 63;
        int tg = tid >> 6;
        float w9[9];
#pragma unroll
        for (int k = 0; k < 9; k++) w9[k] = lw[ch * 9 + k];
        float bias = lb[ch];
        const int hh = token0 >> 7;
        const int ww0 = token0 & 127;
        const int wstart = ww0 + tg * 16;
        const bool hm = hh > 0, hp = hh < (Hh - 1);
        const float* rm = xb + ((size_t)(hh - 1) * Ww) * Cc + ch;
        const float* r0 = xb + ((size_t)hh * Ww) * Cc + ch;
        const float* rp = xb + ((size_t)(hh + 1) * Ww) * Cc + ch;

        float La, Lb2, Lc, Ma, Mb2, Mc, Ra, Rb2, Rc;
        {
            int gw = wstart - 1;
            if ((unsigned)gw < (unsigned)Ww) {
                La = hm ? rm[(size_t)gw * Cc] : 0.f;
                Lb2 = r0[(size_t)gw * Cc];
                Lc = hp ? rp[(size_t)gw * Cc] : 0.f;
            } else { La = Lb2 = Lc = 0.f; }
            gw = wstart;
            Ma = hm ? rm[(size_t)gw * Cc] : 0.f;
            Mb2 = r0[(size_t)gw * Cc];
            Mc = hp ? rp[(size_t)gw * Cc] : 0.f;
        }
#pragma unroll
        for (int j = 0; j < 16; j++) {
            int gw = wstart + j + 1;
            if ((unsigned)gw < (unsigned)Ww) {
                Ra = hm ? rm[(size_t)gw * Cc] : 0.f;
                Rb2 = r0[(size_t)gw * Cc];
                Rc = hp ? rp[(size_t)gw * Cc] : 0.f;
            } else { Ra = Rb2 = Rc = 0.f; }
            float s = bias;
            s = fmaf(w9[0], La, s);  s = fmaf(w9[1], Ma, s);  s = fmaf(w9[2], Ra, s);
            s = fmaf(w9[3], Lb2, s); s = fmaf(w9[4], Mb2, s); s = fmaf(w9[5], Rb2, s);
            s = fmaf(w9[6], Lc, s);  s = fmaf(w9[7], Mc, s);  s = fmaf(w9[8], Rc, s);
            slepe[(tg * 16 + j) * 65 + ch] = s;
            La = Ma; Lb2 = Mb2; Lc = Mc;
            Ma = Ra; Mb2 = Rb2; Mc = Rc;
        }
    }
    __syncthreads();

    // final NCHW write
    {
        int t = tid & 63, hg = tid >> 6;
        int token = token0 + t;
        float* ob = out + (size_t)b * Cc * Nn;
#pragma unroll
        for (int j = 0; j < 16; j++) {
            int ch = hg * 16 + j;
            ob[(size_t)ch * Nn + token] = abuf[t * 65 + ch] + slepe[t * 65 + ch];
        }
    }
}

// ---------------------------------------------------------------------------
extern "C" void kernel_launch(void* const* d_in, const int* in_sizes, int n_in,
                              void* d_out, int out_size) {
    const float* x   = (const float*)d_in[0];
    const float* qkw = (const float*)d_in[3];
    const float* qkb = (const float*)d_in[4];
    const float* lw  = (const float*)d_in[5];
    const float* lb  = (const float*)d_in[6];
    float* out = (float*)d_out;

    int B = in_sizes[0] / (Nn * Cc);
    if (B > BMAX) B = BMAX;

    const int SMEM_K = 12800 * sizeof(float);   // 51200
    const int SMEM_Q = 15296 * sizeof(float);   // 61184

    cudaFuncSetAttribute(k_pass, cudaFuncAttributeMaxDynamicSharedMemorySize, SMEM_K);
    cudaFuncSetAttribute(q_pass, cudaFuncAttributeMaxDynamicSharedMemorySize, SMEM_Q);

    init_tables<<<8, 256>>>();
    k_pass<<<dim3(PB, B), 256, SMEM_K>>>(x, qkw, qkb);
    reduce_pass<<<B, 256>>>();
    q_pass<<<dim3(TILES, B), 256, SMEM_Q>>>(x, qkw, qkb, lw, lb, out);
}